// round 7
// baseline (speedup 1.0000x reference)
#include <cuda_runtime.h>
#include <math.h>

#define NB       4
#define NPER     100000
#define NSOLS    8
#define EBLOCKS  1184          // 8 CTAs * 148 SMs
#define SEGS     296           // EBLOCKS / NB : loadvol segments per batch
#define ROWS_SEG 338           // ceil(NPER / SEGS)

// Per-block partial sums (fully overwritten every call — no zeroing kernel).
// Column-major per accumulator: k_final reads coalesced runs.
__device__ double g_epart[NB * NSOLS * EBLOCKS];
__device__ double g_lpart[NB * NSOLS * EBLOCKS];
__device__ double g_vpart[NB * EBLOCKS];

// ---------------------------------------------------------------------------
// Fused kernel:
//  Prologue (per block): loadvol for a 338-row segment of one batch
//     load[b][s] += mass*rhs*x ; vol[b] += mass
//  Main loop: a_energy[b][s] = sum_nnz val * x[col][s] * x[row][s]
//     - warp loads 32 consecutive (row,col,val) coalesced (3 wf / 32 nnz)
//     - 4 sub-iters distribute them via shuffle to lane quads
//     - lane quad gathers one nnz: lane ql loads float2 = s {2ql, 2ql+1}
//       -> one LDG.64 covers 8 nnz / 8 distinct random 128B lines
// ---------------------------------------------------------------------------
__global__ void k_main(const float* __restrict__ x,
                       const float* __restrict__ rhs,
                       const float* __restrict__ mass,
                       const int*   __restrict__ rows,
                       const int*   __restrict__ cols,
                       const float* __restrict__ vals,
                       int nnz) {
    __shared__ double s_l[NSOLS];
    __shared__ double s_v;
    __shared__ double s_e[NB * NSOLS];

    const int tid  = threadIdx.x;
    const int lane = tid & 31;
    const int blk  = blockIdx.x;

    if (tid < NSOLS)          s_l[tid] = 0.0;
    if (tid == NSOLS)         s_v = 0.0;
    if (tid < NB * NSOLS)     s_e[tid] = 0.0;
    __syncthreads();

    // ---------------- loadvol prologue ----------------
    {
        const int b   = blk & (NB - 1);
        const int seg = blk >> 2;              // 0..SEGS-1
        const float4* x4 = (const float4*)x;
        const float4* r4 = (const float4*)rhs;

        float accL[NSOLS];
#pragma unroll
        for (int s = 0; s < NSOLS; s++) accL[s] = 0.0f;
        float accV = 0.0f;

#pragma unroll
        for (int k = 0; k < 2; k++) {
            int nl = k * 256 + tid;
            int n  = seg * ROWS_SEG + nl;
            if (nl < ROWS_SEG && n < NPER) {
                int idx = b * NPER + n;
                float m = mass[idx];
                float4 xa = x4[idx * 2], xb = x4[idx * 2 + 1];
                float4 ra = r4[idx * 2], rb = r4[idx * 2 + 1];
                accV    += m;
                accL[0] += m * ra.x * xa.x;
                accL[1] += m * ra.y * xa.y;
                accL[2] += m * ra.z * xa.z;
                accL[3] += m * ra.w * xa.w;
                accL[4] += m * rb.x * xb.x;
                accL[5] += m * rb.y * xb.y;
                accL[6] += m * rb.z * xb.z;
                accL[7] += m * rb.w * xb.w;
            }
        }

#pragma unroll
        for (int off = 16; off >= 1; off >>= 1) {
#pragma unroll
            for (int s = 0; s < NSOLS; s++)
                accL[s] += __shfl_xor_sync(0xffffffffu, accL[s], off);
            accV += __shfl_xor_sync(0xffffffffu, accV, off);
        }
        if (lane == 0) {
#pragma unroll
            for (int s = 0; s < NSOLS; s++)
                atomicAdd(&s_l[s], (double)accL[s]);
            atomicAdd(&s_v, (double)accV);
        }
    }

    // ---------------- energy main loop ----------------
    {
        const int ql     = lane & 3;                       // s-pair index
        const int sub    = lane >> 2;                      // nnz-in-subchunk 0..7
        const int warpg  = (blk * blockDim.x + tid) >> 5;  // global warp id
        const int nwarps = (gridDim.x * blockDim.x) >> 5;
        const int nchunk = (nnz + 31) >> 5;

        const float2* x2 = (const float2*)x;

        float acc[NB][2];
#pragma unroll
        for (int bb = 0; bb < NB; bb++) { acc[bb][0] = 0.0f; acc[bb][1] = 0.0f; }

        for (int ch = warpg; ch < nchunk; ch += nwarps) {
            int i = ch * 32 + lane;
            unsigned r_l; unsigned c_l; float v_l;
            if (i < nnz) {
                r_l = (unsigned)__ldcs(&rows[i]);
                c_l = (unsigned)__ldcs(&cols[i]);
                v_l = __ldcs(&vals[i]);
            } else {
                r_l = 0u; c_l = 0u; v_l = 0.0f;
            }

#pragma unroll
            for (int k = 0; k < 4; k++) {
                int src = (k << 3) | sub;
                unsigned r = __shfl_sync(0xffffffffu, r_l, src);
                unsigned c = __shfl_sync(0xffffffffu, c_l, src);
                float    v = __shfl_sync(0xffffffffu, v_l, src);

                float2 xr = __ldg(&x2[r * 4u + (unsigned)ql]);
                float2 xc = __ldg(&x2[c * 4u + (unsigned)ql]);

                int b = (int)(r / (unsigned)NPER);

                float t0 = v * xr.x * xc.x;
                float t1 = v * xr.y * xc.y;

#pragma unroll
                for (int bb = 0; bb < NB; bb++) {
                    if (bb == b) {
                        acc[bb][0] += t0;
                        acc[bb][1] += t1;
                    }
                }
            }
        }

        // butterfly over the 8 nnz-groups (xor 4,8,16 keeps ql fixed)
#pragma unroll
        for (int off = 4; off < 32; off <<= 1) {
#pragma unroll
            for (int bb = 0; bb < NB; bb++) {
                acc[bb][0] += __shfl_xor_sync(0xffffffffu, acc[bb][0], off);
                acc[bb][1] += __shfl_xor_sync(0xffffffffu, acc[bb][1], off);
            }
        }
        if (lane < 4) {
#pragma unroll
            for (int bb = 0; bb < NB; bb++) {
                atomicAdd(&s_e[bb * NSOLS + lane * 2 + 0], (double)acc[bb][0]);
                atomicAdd(&s_e[bb * NSOLS + lane * 2 + 1], (double)acc[bb][1]);
            }
        }
    }
    __syncthreads();

    // ---------------- write per-block partials ----------------
    {
        const int b = blk & (NB - 1);
        if (tid < NB * NSOLS) {
            g_epart[tid * EBLOCKS + blk] = s_e[tid];
            g_lpart[tid * EBLOCKS + blk] = ((tid >> 3) == b) ? s_l[tid & 7] : 0.0;
        }
        if (tid < NB)
            g_vpart[tid * EBLOCKS + blk] = (tid == b) ? s_v : 0.0;
    }
}

// ---------------------------------------------------------------------------
// Final reduction + scalar epilogue. 1 block, 1024 threads.
// Warp w reduces energy/load column w; warps 0..3 also reduce vol.
// ---------------------------------------------------------------------------
__global__ void k_final(float* __restrict__ out) {
    __shared__ double sh_e[NB * NSOLS];
    __shared__ double sh_l[NB * NSOLS];
    __shared__ double sh_v[NB];

    const int tid  = threadIdx.x;
    const int w    = tid >> 5;
    const int lane = tid & 31;

    double e = 0.0, l = 0.0, vv = 0.0;
    for (int i = lane; i < EBLOCKS; i += 32) {
        e += g_epart[w * EBLOCKS + i];
        l += g_lpart[w * EBLOCKS + i];
    }
    if (w < NB)
        for (int i = lane; i < EBLOCKS; i += 32) vv += g_vpart[w * EBLOCKS + i];

#pragma unroll
    for (int off = 16; off >= 1; off >>= 1) {
        e  += __shfl_xor_sync(0xffffffffu, e, off);
        l  += __shfl_xor_sync(0xffffffffu, l, off);
        vv += __shfl_xor_sync(0xffffffffu, vv, off);
    }

    if (lane == 0) {
        sh_e[w] = e;
        sh_l[w] = l;
        if (w < NB) sh_v[w] = vv;
    }
    __syncthreads();

    if (w == 0) {
        // lane = b*8 + s
        double a   = sh_e[lane];
        double L   = sh_l[lane];
        double vol = sh_v[lane >> 3];

        double sigma = L / fmax(a, 1e-4);
        double kkt_e = (0.5 * a * sigma - L) * sigma / vol;
        double cmp_b = sigma * L / vol;
        double contrib = (0.5 * kkt_e - 0.5 * cmp_b) * (1.0 / 32.0);

#pragma unroll
        for (int off = 16; off >= 1; off >>= 1)
            contrib += __shfl_xor_sync(0xffffffffu, contrib, off);

        if (lane == 0) out[0] = (float)contrib;
    }
}

// ---------------------------------------------------------------------------
// Launch
// inputs (metadata order): x_hat, rhs, A_ind(int32), A_val, subspace(unused), mass
// ---------------------------------------------------------------------------
extern "C" void kernel_launch(void* const* d_in, const int* in_sizes, int n_in,
                              void* d_out, int out_size) {
    const float* x_hat = (const float*)d_in[0];
    const float* rhs   = (const float*)d_in[1];
    const int*   A_ind = (const int*)d_in[2];
    const float* A_val = (const float*)d_in[3];
    const float* mass  = (const float*)d_in[5];

    int nnz = in_sizes[3];
    const int* rows = A_ind;          // A_ind[0, :]
    const int* cols = A_ind + nnz;    // A_ind[1, :]

    k_main<<<EBLOCKS, 256>>>(x_hat, rhs, mass, rows, cols, A_val, nnz);
    k_final<<<1, 1024>>>((float*)d_out);
}

// round 8
// speedup vs baseline: 1.1575x; 1.1575x over previous
#include <cuda_runtime.h>
#include <math.h>

#define NB       4
#define NPER     100000
#define NSOLS    8
#define EBLOCKS  1184          // 8 CTAs * 148 SMs
#define SEGS     296           // EBLOCKS / NB : loadvol segments per batch
#define ROWS_SEG 338           // ceil(NPER / SEGS); 296*338 = 100048 >= 100000

// Per-block partial sums (fully overwritten every call — no zeroing kernel).
// Column-major per accumulator: k_final reads coalesced runs.
__device__ double g_epart[NB * NSOLS * EBLOCKS];   // [32][1184]
__device__ double g_lpart[NB * NSOLS * SEGS];      // [32][296]
__device__ double g_vpart[NB * SEGS];              // [4][296]

// ---------------------------------------------------------------------------
// Fused kernel:
//  Prologue (per block): loadvol for a 338-row segment of one batch
//     load[b][s] += mass*rhs*x ; vol[b] += mass   (hides under gather loop)
//  Main loop (R6-style): a_energy[b][s] = sum_nnz val * x[col][s] * x[row][s]
//     lane quad handles one nnz; lane ql loads float2 = s {2ql, 2ql+1}
//     -> one LDG.64 covers 8 nnz / 8 distinct random 128B lines.
//     Index/val loads replicate x4 across the quad but coalesce to one
//     32B sector each (3 wavefronts per 8 nnz) — cheaper than shuffles.
// ---------------------------------------------------------------------------
__global__ void k_main(const float* __restrict__ x,
                       const float* __restrict__ rhs,
                       const float* __restrict__ mass,
                       const int*   __restrict__ rows,
                       const int*   __restrict__ cols,
                       const float* __restrict__ vals,
                       int nnz) {
    __shared__ double s_l[NSOLS];
    __shared__ double s_v;
    __shared__ double s_e[NB * NSOLS];

    const int tid  = threadIdx.x;
    const int lane = tid & 31;
    const int blk  = blockIdx.x;
    const int b    = blk & (NB - 1);
    const int seg  = blk >> 2;             // 0..SEGS-1

    if (tid < NSOLS)      s_l[tid] = 0.0;
    if (tid == NSOLS)     s_v = 0.0;
    if (tid < NB * NSOLS) s_e[tid] = 0.0;
    __syncthreads();

    // ---------------- loadvol prologue ----------------
    {
        const float4* x4 = (const float4*)x;
        const float4* r4 = (const float4*)rhs;

        float accL[NSOLS];
#pragma unroll
        for (int s = 0; s < NSOLS; s++) accL[s] = 0.0f;
        float accV = 0.0f;

#pragma unroll
        for (int k = 0; k < 2; k++) {
            int nl = k * 256 + tid;
            int n  = seg * ROWS_SEG + nl;
            if (nl < ROWS_SEG && n < NPER) {
                int idx = b * NPER + n;
                float m = mass[idx];
                float4 xa = x4[idx * 2], xb = x4[idx * 2 + 1];
                float4 ra = r4[idx * 2], rb = r4[idx * 2 + 1];
                accV    += m;
                accL[0] += m * ra.x * xa.x;
                accL[1] += m * ra.y * xa.y;
                accL[2] += m * ra.z * xa.z;
                accL[3] += m * ra.w * xa.w;
                accL[4] += m * rb.x * xb.x;
                accL[5] += m * rb.y * xb.y;
                accL[6] += m * rb.z * xb.z;
                accL[7] += m * rb.w * xb.w;
            }
        }

#pragma unroll
        for (int off = 16; off >= 1; off >>= 1) {
#pragma unroll
            for (int s = 0; s < NSOLS; s++)
                accL[s] += __shfl_xor_sync(0xffffffffu, accL[s], off);
            accV += __shfl_xor_sync(0xffffffffu, accV, off);
        }
        if (lane == 0) {
#pragma unroll
            for (int s = 0; s < NSOLS; s++)
                atomicAdd(&s_l[s], (double)accL[s]);
            atomicAdd(&s_v, (double)accV);
        }
    }

    // ---------------- energy main loop (R6 form) ----------------
    {
        const int gtid  = blk * blockDim.x + tid;
        const int ql    = gtid & 3;                   // s-pair index 0..3
        const int quad  = gtid >> 2;                  // starting nnz index
        const int qstep = (gridDim.x * blockDim.x) >> 2;

        const float2* x2 = (const float2*)x;

        float acc[NB][2];
#pragma unroll
        for (int bb = 0; bb < NB; bb++) { acc[bb][0] = 0.0f; acc[bb][1] = 0.0f; }

        for (int i = quad; i < nnz; i += qstep) {
            unsigned r = (unsigned)__ldcs(&rows[i]);  // streaming, no reuse
            unsigned c = (unsigned)__ldcs(&cols[i]);
            float    v = __ldcs(&vals[i]);

            float2 xr = __ldg(&x2[r * 4u + (unsigned)ql]);
            float2 xc = __ldg(&x2[c * 4u + (unsigned)ql]);

            int bnz = (int)(r / (unsigned)NPER);

            float t0 = v * xr.x * xc.x;
            float t1 = v * xr.y * xc.y;

#pragma unroll
            for (int bb = 0; bb < NB; bb++) {
                if (bb == bnz) {
                    acc[bb][0] += t0;
                    acc[bb][1] += t1;
                }
            }
        }

        // butterfly over the 8 quads of the warp (xor 4,8,16 keeps ql fixed)
#pragma unroll
        for (int off = 4; off < 32; off <<= 1) {
#pragma unroll
            for (int bb = 0; bb < NB; bb++) {
                acc[bb][0] += __shfl_xor_sync(0xffffffffu, acc[bb][0], off);
                acc[bb][1] += __shfl_xor_sync(0xffffffffu, acc[bb][1], off);
            }
        }
        if (lane < 4) {
#pragma unroll
            for (int bb = 0; bb < NB; bb++) {
                atomicAdd(&s_e[bb * NSOLS + lane * 2 + 0], (double)acc[bb][0]);
                atomicAdd(&s_e[bb * NSOLS + lane * 2 + 1], (double)acc[bb][1]);
            }
        }
    }
    __syncthreads();

    // ---------------- write per-block partials (compact) ----------------
    if (tid < NB * NSOLS) {
        g_epart[tid * EBLOCKS + blk] = s_e[tid];
        if ((tid >> 3) == b)
            g_lpart[tid * SEGS + seg] = s_l[tid & 7];
    }
    if (tid == b)
        g_vpart[b * SEGS + seg] = s_v;
}

// ---------------------------------------------------------------------------
// Final reduction + scalar epilogue. 1 block, 1024 threads.
// Warp w reduces energy column w (1184 entries) and load column w (296);
// warps 0..3 also reduce vol. Then warp 0 computes the epilogue in parallel.
// ---------------------------------------------------------------------------
__global__ void k_final(float* __restrict__ out) {
    __shared__ double sh_e[NB * NSOLS];
    __shared__ double sh_l[NB * NSOLS];
    __shared__ double sh_v[NB];

    const int tid  = threadIdx.x;
    const int w    = tid >> 5;
    const int lane = tid & 31;

    double e = 0.0, l = 0.0, vv = 0.0;
#pragma unroll 4
    for (int i = lane; i < EBLOCKS; i += 32) e += g_epart[w * EBLOCKS + i];
#pragma unroll 4
    for (int i = lane; i < SEGS; i += 32)    l += g_lpart[w * SEGS + i];
    if (w < NB) {
#pragma unroll 4
        for (int i = lane; i < SEGS; i += 32) vv += g_vpart[w * SEGS + i];
    }

#pragma unroll
    for (int off = 16; off >= 1; off >>= 1) {
        e  += __shfl_xor_sync(0xffffffffu, e, off);
        l  += __shfl_xor_sync(0xffffffffu, l, off);
        vv += __shfl_xor_sync(0xffffffffu, vv, off);
    }

    if (lane == 0) {
        sh_e[w] = e;
        sh_l[w] = l;
        if (w < NB) sh_v[w] = vv;
    }
    __syncthreads();

    if (w == 0) {
        // lane = b*8 + s
        double a   = sh_e[lane];
        double L   = sh_l[lane];
        double vol = sh_v[lane >> 3];

        double sigma = L / fmax(a, 1e-4);
        double kkt_e = (0.5 * a * sigma - L) * sigma / vol;
        double cmp_b = sigma * L / vol;
        double contrib = (0.5 * kkt_e - 0.5 * cmp_b) * (1.0 / 32.0);

#pragma unroll
        for (int off = 16; off >= 1; off >>= 1)
            contrib += __shfl_xor_sync(0xffffffffu, contrib, off);

        if (lane == 0) out[0] = (float)contrib;
    }
}

// ---------------------------------------------------------------------------
// Launch
// inputs (metadata order): x_hat, rhs, A_ind(int32), A_val, subspace(unused), mass
// ---------------------------------------------------------------------------
extern "C" void kernel_launch(void* const* d_in, const int* in_sizes, int n_in,
                              void* d_out, int out_size) {
    const float* x_hat = (const float*)d_in[0];
    const float* rhs   = (const float*)d_in[1];
    const int*   A_ind = (const int*)d_in[2];
    const float* A_val = (const float*)d_in[3];
    const float* mass  = (const float*)d_in[5];

    int nnz = in_sizes[3];
    const int* rows = A_ind;          // A_ind[0, :]
    const int* cols = A_ind + nnz;    // A_ind[1, :]

    k_main<<<EBLOCKS, 256>>>(x_hat, rhs, mass, rows, cols, A_val, nnz);
    k_final<<<1, 1024>>>((float*)d_out);
}